// round 1
// baseline (speedup 1.0000x reference)
#include <cuda_runtime.h>
#include <cuda_bf16.h>

#define NN 100000
#define NE 1600000
#define D 64
#define EPS 1e-5f

// Scratch (allocation-free rule: __device__ globals)
__device__ float g_h[(size_t)NN * D];   // SpMM output
__device__ float g_sum[D];
__device__ float g_sq[D];

// ---------------------------------------------------------------------------
// Kernel 1: zero h scratch + stats
// ---------------------------------------------------------------------------
__global__ void zero_kernel() {
    size_t idx = (size_t)blockIdx.x * blockDim.x + threadIdx.x;
    size_t total = (size_t)NN * D / 4;
    if (idx < total) {
        ((float4*)g_h)[idx] = make_float4(0.f, 0.f, 0.f, 0.f);
    }
    if (blockIdx.x == 0 && threadIdx.x < D) {
        g_sum[threadIdx.x] = 0.f;
        g_sq[threadIdx.x]  = 0.f;
    }
}

// ---------------------------------------------------------------------------
// Kernel 2: COO SpMM, 16 threads per edge, one float4 per thread,
// vector atomicAdd (sm_90+) into g_h[row]
// ---------------------------------------------------------------------------
__global__ void spmm_kernel(const float* __restrict__ x,
                            const float* __restrict__ val,
                            const int*   __restrict__ row,
                            const int*   __restrict__ col) {
    unsigned gid = blockIdx.x * blockDim.x + threadIdx.x;
    unsigned e = gid >> 4;
    unsigned q = gid & 15;
    if (e >= NE) return;
    int r = row[e];
    int c = col[e];
    float a = val[e];
    float4 xv = ((const float4*)(x + (size_t)c * D))[q];
    float4 contrib = make_float4(a * xv.x, a * xv.y, a * xv.z, a * xv.w);
    atomicAdd(((float4*)(g_h + (size_t)r * D)) + q, contrib);
}

// ---------------------------------------------------------------------------
// Kernel 3: y = g_h @ W^T + b + x  (one warp per row, 2 cols per lane),
// plus per-column sum / sumsq accumulation for BatchNorm.
// W^T staged in smem: Wt[k][j] so lanes read consecutive float2 -> no conflicts.
// ---------------------------------------------------------------------------
__global__ void gemm_kernel(const float* __restrict__ x,
                            const float* __restrict__ W,
                            const float* __restrict__ b,
                            float* __restrict__ y) {
    __shared__ float Wt[D * D];     // Wt[k*D + j] = W[j*D + k]
    __shared__ float bs[D];
    __shared__ float hs[8][D];      // per-warp staging of h row
    __shared__ float rs[D];         // block partial sums
    __shared__ float rq[D];         // block partial sumsq

    int tid = threadIdx.x;
    for (int i = tid; i < D * D; i += blockDim.x) {
        int j = i >> 6;
        int k = i & 63;
        Wt[k * D + j] = W[j * D + k];
    }
    if (tid < D) { bs[tid] = b[tid]; rs[tid] = 0.f; rq[tid] = 0.f; }
    __syncthreads();

    int w = tid >> 5;
    int lane = tid & 31;
    int warp_global = blockIdx.x * 8 + w;
    int nwarps = gridDim.x * 8;

    float s0 = 0.f, s1 = 0.f, q0 = 0.f, q1 = 0.f;

    for (int r = warp_global; r < NN; r += nwarps) {
        float2 hv = ((const float2*)(g_h + (size_t)r * D))[lane];
        ((float2*)hs[w])[lane] = hv;
        __syncwarp();

        float2 xv = ((const float2*)(x + (size_t)r * D))[lane];
        float a0 = bs[2 * lane]     + xv.x;
        float a1 = bs[2 * lane + 1] + xv.y;

        #pragma unroll
        for (int k = 0; k < D; k++) {
            float hk = hs[w][k];                       // broadcast
            float2 wv = ((const float2*)(Wt + k * D))[lane];
            a0 = fmaf(hk, wv.x, a0);
            a1 = fmaf(hk, wv.y, a1);
        }

        ((float2*)(y + (size_t)r * D))[lane] = make_float2(a0, a1);
        s0 += a0; s1 += a1;
        q0 = fmaf(a0, a0, q0);
        q1 = fmaf(a1, a1, q1);
        __syncwarp();   // protect hs[w] before next iteration's store
    }

    // block-level reduction into smem, then one global atomic per column
    atomicAdd(&rs[2 * lane],     s0);
    atomicAdd(&rs[2 * lane + 1], s1);
    atomicAdd(&rq[2 * lane],     q0);
    atomicAdd(&rq[2 * lane + 1], q1);
    __syncthreads();
    if (tid < D) {
        atomicAdd(&g_sum[tid], rs[tid]);
        atomicAdd(&g_sq[tid],  rq[tid]);
    }
}

// ---------------------------------------------------------------------------
// Kernel 4: BatchNorm (batch stats, biased var) + ReLU, in-place on y.
// Each block recomputes scale/shift from the 64-entry stats (cheap, redundant).
// ---------------------------------------------------------------------------
__global__ void bn_kernel(const float* __restrict__ gamma,
                          const float* __restrict__ beta,
                          float* __restrict__ y) {
    __shared__ float sc[D];
    __shared__ float sh[D];
    int tid = threadIdx.x;
    if (tid < D) {
        const float invN = 1.0f / (float)NN;
        float mean = g_sum[tid] * invN;
        float var  = g_sq[tid] * invN - mean * mean;
        float s = gamma[tid] * rsqrtf(var + EPS);
        sc[tid] = s;
        sh[tid] = beta[tid] - mean * s;
    }
    __syncthreads();

    size_t idx = (size_t)blockIdx.x * blockDim.x + threadIdx.x;
    size_t total = (size_t)NN * D / 4;
    if (idx < total) {
        float4 v = ((float4*)y)[idx];
        int c = (int)((idx * 4) & 63);
        v.x = fmaxf(fmaf(v.x, sc[c],     sh[c]),     0.f);
        v.y = fmaxf(fmaf(v.y, sc[c + 1], sh[c + 1]), 0.f);
        v.z = fmaxf(fmaf(v.z, sc[c + 2], sh[c + 2]), 0.f);
        v.w = fmaxf(fmaf(v.w, sc[c + 3], sh[c + 3]), 0.f);
        ((float4*)y)[idx] = v;
    }
}

// ---------------------------------------------------------------------------
// Launch. Input order per metadata: x, adj_val, W, b, gamma, beta, adj_row, adj_col
// ---------------------------------------------------------------------------
extern "C" void kernel_launch(void* const* d_in, const int* in_sizes, int n_in,
                              void* d_out, int out_size) {
    const float* x       = (const float*)d_in[0];
    const float* adj_val = (const float*)d_in[1];
    const float* W       = (const float*)d_in[2];
    const float* b       = (const float*)d_in[3];
    const float* gamma   = (const float*)d_in[4];
    const float* beta    = (const float*)d_in[5];
    const int*   adj_row = (const int*)d_in[6];
    const int*   adj_col = (const int*)d_in[7];
    float* y = (float*)d_out;

    // 1) zero scratch
    {
        int total4 = NN * D / 4;                // 1.6M float4
        int blocks = (total4 + 255) / 256;
        zero_kernel<<<blocks, 256>>>();
    }
    // 2) SpMM scatter (16 threads/edge)
    {
        long long threads = (long long)NE * 16; // 25.6M
        int blocks = (int)((threads + 255) / 256);
        spmm_kernel<<<blocks, 256>>>(x, adj_val, adj_row, adj_col);
    }
    // 3) GEMM + bias + residual + stats
    {
        gemm_kernel<<<512, 256>>>(x, W, b, y);
    }
    // 4) BN + ReLU in-place
    {
        int total4 = NN * D / 4;
        int blocks = (total4 + 255) / 256;
        bn_kernel<<<blocks, 256>>>(gamma, beta, y);
    }
}

// round 2
// speedup vs baseline: 1.0562x; 1.0562x over previous
#include <cuda_runtime.h>
#include <cuda_bf16.h>

#define NN 100000
#define NE 1600000
#define D 64
#define EPS 1e-5f
#define SCAN_BLK 1024
#define NB ((NN + SCAN_BLK - 1) / SCAN_BLK)   // 98

// Scratch (__device__ globals; no allocs allowed)
__device__ int   g_cnt[NN];
__device__ int   g_rowstart[NN + 1];
__device__ int   g_woff[NN];
__device__ int   g_blksum[128];
__device__ int2  g_edge[NE];      // (col, val-bits), row-sorted
__device__ float g_sum[D];
__device__ float g_sq[D];

// ---------------------------------------------------------------------------
// 1) zero counters + stats
// ---------------------------------------------------------------------------
__global__ void zero_cnt_kernel() {
    int i = blockIdx.x * blockDim.x + threadIdx.x;
    if (i < NN) g_cnt[i] = 0;
    if (i < D) { g_sum[i] = 0.f; g_sq[i] = 0.f; }
}

// ---------------------------------------------------------------------------
// 2) histogram of adj_row
// ---------------------------------------------------------------------------
__global__ void hist_kernel(const int* __restrict__ row) {
    int e = blockIdx.x * blockDim.x + threadIdx.x;
    if (e < NE) atomicAdd(&g_cnt[row[e]], 1);
}

// ---------------------------------------------------------------------------
// 3a) per-block exclusive scan of g_cnt (1024 elems/block)
// ---------------------------------------------------------------------------
__global__ void scan_local_kernel() {
    int i = blockIdx.x * SCAN_BLK + threadIdx.x;
    int v = (i < NN) ? g_cnt[i] : 0;
    int lane = threadIdx.x & 31, w = threadIdx.x >> 5;
    int s = v;
    #pragma unroll
    for (int d = 1; d < 32; d <<= 1) {
        int t = __shfl_up_sync(0xFFFFFFFFu, s, d);
        if (lane >= d) s += t;
    }
    __shared__ int wsum[32];
    if (lane == 31) wsum[w] = s;
    __syncthreads();
    if (w == 0) {
        int ws = wsum[lane];
        #pragma unroll
        for (int d = 1; d < 32; d <<= 1) {
            int t = __shfl_up_sync(0xFFFFFFFFu, ws, d);
            if (lane >= d) ws += t;
        }
        wsum[lane] = ws;
    }
    __syncthreads();
    int incl = s + (w > 0 ? wsum[w - 1] : 0);
    if (i < NN) g_rowstart[i] = incl - v;          // local exclusive
    if (threadIdx.x == SCAN_BLK - 1) g_blksum[blockIdx.x] = incl;
}

// ---------------------------------------------------------------------------
// 3b) scan block sums (1 block, 128 threads covers NB=98)
// ---------------------------------------------------------------------------
__global__ void scan_top_kernel() {
    int tid = threadIdx.x;
    int v = (tid < NB) ? g_blksum[tid] : 0;
    int lane = tid & 31, w = tid >> 5;
    int s = v;
    #pragma unroll
    for (int d = 1; d < 32; d <<= 1) {
        int t = __shfl_up_sync(0xFFFFFFFFu, s, d);
        if (lane >= d) s += t;
    }
    __shared__ int wsum[4];
    if (lane == 31) wsum[w] = s;
    __syncthreads();
    int off = 0;
    for (int k = 0; k < w; k++) off += wsum[k];
    int incl = s + off;
    if (tid < NB) g_blksum[tid] = incl - v;        // exclusive
}

// ---------------------------------------------------------------------------
// 3c) add block offsets; init write cursors; rowstart[NN]=NE
// ---------------------------------------------------------------------------
__global__ void scan_add_kernel() {
    int i = blockIdx.x * blockDim.x + threadIdx.x;
    if (i < NN) {
        int rv = g_rowstart[i] + g_blksum[i >> 10];
        g_rowstart[i] = rv;
        g_woff[i] = rv;
    }
    if (i == 0) g_rowstart[NN] = NE;
}

// ---------------------------------------------------------------------------
// 4) scatter edges into row-sorted order
// ---------------------------------------------------------------------------
__global__ void scatter_kernel(const float* __restrict__ val,
                               const int*   __restrict__ row,
                               const int*   __restrict__ col) {
    int e = blockIdx.x * blockDim.x + threadIdx.x;
    if (e >= NE) return;
    int r = row[e];
    int p = atomicAdd(&g_woff[r], 1);
    g_edge[p] = make_int2(col[e], __float_as_int(val[e]));
}

// ---------------------------------------------------------------------------
// 5) fused: h = A@x (CSR gather, warp/row) ; y = h@W^T + b + x ; BN stats
// ---------------------------------------------------------------------------
__global__ void fused_kernel(const float* __restrict__ x,
                             const float* __restrict__ W,
                             const float* __restrict__ b,
                             float* __restrict__ y) {
    __shared__ float Wt[D * D];     // Wt[k*D + j] = W[j*D + k]
    __shared__ float bs[D];
    __shared__ float hs[8][D];
    __shared__ float rs[D];
    __shared__ float rq[D];

    int tid = threadIdx.x;
    for (int i = tid; i < D * D; i += blockDim.x) {
        int j = i >> 6, k = i & 63;
        Wt[k * D + j] = W[j * D + k];
    }
    if (tid < D) { bs[tid] = b[tid]; rs[tid] = 0.f; rq[tid] = 0.f; }
    __syncthreads();

    int w = tid >> 5;
    int lane = tid & 31;
    int warp_global = blockIdx.x * 8 + w;
    int nwarps = gridDim.x * 8;
    const float2* xb = (const float2*)x;

    float s0 = 0.f, s1 = 0.f, q0 = 0.f, q1 = 0.f;

    for (int r = warp_global; r < NN; r += nwarps) {
        int start = g_rowstart[r];
        int end   = g_rowstart[r + 1];

        float hx = 0.f, hy = 0.f;
        int j = start;
        for (; j + 3 < end; j += 4) {
            int2 e0 = g_edge[j], e1 = g_edge[j + 1], e2 = g_edge[j + 2], e3 = g_edge[j + 3];
            float2 x0 = xb[e0.x * 32 + lane];
            float2 x1 = xb[e1.x * 32 + lane];
            float2 x2 = xb[e2.x * 32 + lane];
            float2 x3 = xb[e3.x * 32 + lane];
            float v0 = __int_as_float(e0.y), v1 = __int_as_float(e1.y);
            float v2 = __int_as_float(e2.y), v3 = __int_as_float(e3.y);
            hx = fmaf(v0, x0.x, hx); hy = fmaf(v0, x0.y, hy);
            hx = fmaf(v1, x1.x, hx); hy = fmaf(v1, x1.y, hy);
            hx = fmaf(v2, x2.x, hx); hy = fmaf(v2, x2.y, hy);
            hx = fmaf(v3, x3.x, hx); hy = fmaf(v3, x3.y, hy);
        }
        for (; j < end; j++) {
            int2 e0 = g_edge[j];
            float2 x0 = xb[e0.x * 32 + lane];
            float v0 = __int_as_float(e0.y);
            hx = fmaf(v0, x0.x, hx); hy = fmaf(v0, x0.y, hy);
        }

        ((float2*)hs[w])[lane] = make_float2(hx, hy);
        __syncwarp();

        float2 xv = xb[(size_t)r * 32 + lane];
        float a0 = bs[2 * lane]     + xv.x;
        float a1 = bs[2 * lane + 1] + xv.y;

        #pragma unroll
        for (int k = 0; k < D; k++) {
            float hk = hs[w][k];
            float2 wv = ((const float2*)(Wt + k * D))[lane];
            a0 = fmaf(hk, wv.x, a0);
            a1 = fmaf(hk, wv.y, a1);
        }

        ((float2*)(y + (size_t)r * D))[lane] = make_float2(a0, a1);
        s0 += a0; s1 += a1;
        q0 = fmaf(a0, a0, q0);
        q1 = fmaf(a1, a1, q1);
        __syncwarp();
    }

    atomicAdd(&rs[2 * lane],     s0);
    atomicAdd(&rs[2 * lane + 1], s1);
    atomicAdd(&rq[2 * lane],     q0);
    atomicAdd(&rq[2 * lane + 1], q1);
    __syncthreads();
    if (tid < D) {
        atomicAdd(&g_sum[tid], rs[tid]);
        atomicAdd(&g_sq[tid],  rq[tid]);
    }
}

// ---------------------------------------------------------------------------
// 6) BatchNorm + ReLU in-place
// ---------------------------------------------------------------------------
__global__ void bn_kernel(const float* __restrict__ gamma,
                          const float* __restrict__ beta,
                          float* __restrict__ y) {
    __shared__ float sc[D];
    __shared__ float sh[D];
    int tid = threadIdx.x;
    if (tid < D) {
        const float invN = 1.0f / (float)NN;
        float mean = g_sum[tid] * invN;
        float var  = g_sq[tid] * invN - mean * mean;
        float s = gamma[tid] * rsqrtf(var + EPS);
        sc[tid] = s;
        sh[tid] = beta[tid] - mean * s;
    }
    __syncthreads();

    size_t idx = (size_t)blockIdx.x * blockDim.x + threadIdx.x;
    size_t total = (size_t)NN * D / 4;
    if (idx < total) {
        float4 v = ((float4*)y)[idx];
        int c = (int)((idx * 4) & 63);
        v.x = fmaxf(fmaf(v.x, sc[c],     sh[c]),     0.f);
        v.y = fmaxf(fmaf(v.y, sc[c + 1], sh[c + 1]), 0.f);
        v.z = fmaxf(fmaf(v.z, sc[c + 2], sh[c + 2]), 0.f);
        v.w = fmaxf(fmaf(v.w, sc[c + 3], sh[c + 3]), 0.f);
        ((float4*)y)[idx] = v;
    }
}

// ---------------------------------------------------------------------------
// Launch. Input order: x, adj_val, W, b, gamma, beta, adj_row, adj_col
// ---------------------------------------------------------------------------
extern "C" void kernel_launch(void* const* d_in, const int* in_sizes, int n_in,
                              void* d_out, int out_size) {
    const float* x       = (const float*)d_in[0];
    const float* adj_val = (const float*)d_in[1];
    const float* W       = (const float*)d_in[2];
    const float* b       = (const float*)d_in[3];
    const float* gamma   = (const float*)d_in[4];
    const float* beta    = (const float*)d_in[5];
    const int*   adj_row = (const int*)d_in[6];
    const int*   adj_col = (const int*)d_in[7];
    float* y = (float*)d_out;

    zero_cnt_kernel<<<(NN + 255) / 256, 256>>>();
    hist_kernel<<<(NE + 255) / 256, 256>>>(adj_row);
    scan_local_kernel<<<NB, SCAN_BLK>>>();
    scan_top_kernel<<<1, 128>>>();
    scan_add_kernel<<<(NN + 255) / 256, 256>>>();
    scatter_kernel<<<(NE + 255) / 256, 256>>>(adj_val, adj_row, adj_col);
    fused_kernel<<<1536, 256>>>(x, W, b, y);
    bn_kernel<<<(NN * D / 4 + 255) / 256, 256>>>(gamma, beta, y);
}

// round 3
// speedup vs baseline: 1.2399x; 1.1739x over previous
#include <cuda_runtime.h>
#include <cuda_bf16.h>

#define NN 100000
#define NE 1600000
#define D 64
#define EPS 1e-5f
#define SCAN_BLK 1024
#define NB 98               // ceil(NN / SCAN_BLK)

// Scratch (__device__ globals; no allocs allowed). Zero-initialized at load.
__device__ int   g_cnt[NN];
__device__ int   g_rowstart[NN + 1];
__device__ int   g_woff[NN];
__device__ int   g_blksum[128];
__device__ int2  g_edge[NE];      // (col, val-bits), row-sorted
__device__ float g_sum[D];
__device__ float g_sq[D];

// Packed fp32x2 helpers (Blackwell FFMA2 only reachable via PTX)
#define FMA2(d, a, b, c) asm("fma.rn.f32x2 %0, %1, %2, %3;" : "=l"(d) : "l"(a), "l"(b), "l"(c))
#define PACK2U(d, lo, hi) asm("mov.b64 %0, {%1, %2};" : "=l"(d) : "r"(lo), "r"(hi))
#define UNPACK2U(lo, hi, v) asm("mov.b64 {%0, %1}, %2;" : "=r"(lo), "=r"(hi) : "l"(v))

// ---------------------------------------------------------------------------
// 1) histogram of adj_row (g_cnt zeroed by previous call's scan_local /
//    zero-initialized globals on first call)
// ---------------------------------------------------------------------------
__global__ void hist_kernel(const int* __restrict__ row) {
    int t = blockIdx.x * blockDim.x + threadIdx.x;
    if (t < NE / 4) {
        int4 r4 = ((const int4*)row)[t];
        atomicAdd(&g_cnt[r4.x], 1);
        atomicAdd(&g_cnt[r4.y], 1);
        atomicAdd(&g_cnt[r4.z], 1);
        atomicAdd(&g_cnt[r4.w], 1);
    }
}

// ---------------------------------------------------------------------------
// 2) per-block exclusive scan of g_cnt (1024/block); zero g_cnt for next call
// ---------------------------------------------------------------------------
__global__ void scan_local_kernel() {
    int i = blockIdx.x * SCAN_BLK + threadIdx.x;
    int v = (i < NN) ? g_cnt[i] : 0;
    if (i < NN) g_cnt[i] = 0;           // reset for next graph replay
    int lane = threadIdx.x & 31, w = threadIdx.x >> 5;
    int s = v;
    #pragma unroll
    for (int d = 1; d < 32; d <<= 1) {
        int t = __shfl_up_sync(0xFFFFFFFFu, s, d);
        if (lane >= d) s += t;
    }
    __shared__ int wsum[32];
    if (lane == 31) wsum[w] = s;
    __syncthreads();
    if (w == 0) {
        int ws = wsum[lane];
        #pragma unroll
        for (int d = 1; d < 32; d <<= 1) {
            int t = __shfl_up_sync(0xFFFFFFFFu, ws, d);
            if (lane >= d) ws += t;
        }
        wsum[lane] = ws;
    }
    __syncthreads();
    int incl = s + (w > 0 ? wsum[w - 1] : 0);
    if (i < NN) g_rowstart[i] = incl - v;          // local exclusive
    if (threadIdx.x == SCAN_BLK - 1) g_blksum[blockIdx.x] = incl;
}

// ---------------------------------------------------------------------------
// 3) scan_add: each block redundantly scans the 98 block sums, adds its
//    offset, initializes write cursors; block 0 also sets rowstart[NN] and
//    zeroes BN stats for this call.
// ---------------------------------------------------------------------------
__global__ void scan_add_kernel() {
    __shared__ int top[128];
    __shared__ int wsum[4];
    int tid = threadIdx.x;
    if (tid < 128) {
        int v = (tid < NB) ? g_blksum[tid] : 0;
        int lane = tid & 31, w = tid >> 5;
        int s = v;
        #pragma unroll
        for (int d = 1; d < 32; d <<= 1) {
            int t = __shfl_up_sync(0xFFFFFFFFu, s, d);
            if (lane >= d) s += t;
        }
        if (lane == 31) wsum[w] = s;
        top[tid] = s - v;                // warp-local exclusive
    }
    __syncthreads();
    if (tid < 128) {
        int w = tid >> 5;
        int off = 0;
        for (int k = 0; k < w; k++) off += wsum[k];
        top[tid] += off;                 // global exclusive over blocks
    }
    __syncthreads();
    int boff = top[blockIdx.x];
    int i = blockIdx.x * SCAN_BLK + tid;
    if (i < NN) {
        int rv = g_rowstart[i] + boff;
        g_rowstart[i] = rv;
        g_woff[i] = rv;
    }
    if (blockIdx.x == 0) {
        if (tid == 0) g_rowstart[NN] = NE;
        if (tid < D) { g_sum[tid] = 0.f; g_sq[tid] = 0.f; }
    }
}

// ---------------------------------------------------------------------------
// 4) scatter edges into row-sorted order (4 edges/thread)
// ---------------------------------------------------------------------------
__global__ void scatter_kernel(const float* __restrict__ val,
                               const int*   __restrict__ row,
                               const int*   __restrict__ col) {
    int t = blockIdx.x * blockDim.x + threadIdx.x;
    if (t >= NE / 4) return;
    int4   r4 = ((const int4*)row)[t];
    int4   c4 = ((const int4*)col)[t];
    float4 v4 = ((const float4*)val)[t];
    int p;
    p = atomicAdd(&g_woff[r4.x], 1); g_edge[p] = make_int2(c4.x, __float_as_int(v4.x));
    p = atomicAdd(&g_woff[r4.y], 1); g_edge[p] = make_int2(c4.y, __float_as_int(v4.y));
    p = atomicAdd(&g_woff[r4.z], 1); g_edge[p] = make_int2(c4.z, __float_as_int(v4.z));
    p = atomicAdd(&g_woff[r4.w], 1); g_edge[p] = make_int2(c4.w, __float_as_int(v4.w));
}

// ---------------------------------------------------------------------------
// 5) fused: h = A@x (CSR gather, 4 rows/warp) ; y = h@W^T + b + x ; BN stats
//    GEMM uses packed f32x2 FMA + float4 smem traffic.
// ---------------------------------------------------------------------------
__global__ void __launch_bounds__(256) fused_kernel(const float* __restrict__ x,
                                                    const float* __restrict__ W,
                                                    const float* __restrict__ b,
                                                    float* __restrict__ y) {
    // Wp[p*32+l] = (Wt[2p][2l], Wt[2p][2l+1], Wt[2p+1][2l], Wt[2p+1][2l+1]),
    // Wt[k][j] = W[j*D+k]
    __shared__ float4 Wp[32 * 32];     // 16KB
    __shared__ float4 h4s[8][64];      // 8KB: h4s[w][k] = h of 4 rows at col k
    __shared__ float  bs[D];
    __shared__ float  rs[D];
    __shared__ float  rq[D];

    int tid = threadIdx.x;
    for (int idx = tid; idx < 1024; idx += 256) {
        int p = idx >> 5, l = idx & 31;
        Wp[idx] = make_float4(W[(2 * l) * D + 2 * p],     W[(2 * l + 1) * D + 2 * p],
                              W[(2 * l) * D + 2 * p + 1], W[(2 * l + 1) * D + 2 * p + 1]);
    }
    if (tid < D) { bs[tid] = b[tid]; rs[tid] = 0.f; rq[tid] = 0.f; }
    __syncthreads();

    int w = tid >> 5;
    int lane = tid & 31;
    int wg = blockIdx.x * 8 + w;
    int nw = gridDim.x * 8;
    const unsigned long long* xb8 = (const unsigned long long*)x;  // (x[2l],x[2l+1]) pairs
    const ulonglong2* Wp2 = (const ulonglong2*)Wp;
    float4* h4w = h4s[w];

    float s0 = 0.f, s1 = 0.f, q0 = 0.f, q1 = 0.f;

    for (int r0 = wg * 4; r0 < NN; r0 += nw * 4) {   // NN % 4 == 0
        // --- gather 4 rows; lane keeps its 2 columns in regs across rows ---
        float hx[4], hy[4];
        #pragma unroll
        for (int rr = 0; rr < 4; rr++) {
            int r = r0 + rr;
            int start = g_rowstart[r];
            int end   = g_rowstart[r + 1];
            unsigned long long hp = 0ull;            // packed (hx,hy)
            int j = start;
            for (; j + 3 < end; j += 4) {
                int2 e0 = g_edge[j],     e1 = g_edge[j + 1];
                int2 e2 = g_edge[j + 2], e3 = g_edge[j + 3];
                unsigned long long x0 = xb8[(size_t)e0.x * 32 + lane];
                unsigned long long x1 = xb8[(size_t)e1.x * 32 + lane];
                unsigned long long x2 = xb8[(size_t)e2.x * 32 + lane];
                unsigned long long x3 = xb8[(size_t)e3.x * 32 + lane];
                unsigned long long v0, v1, v2, v3;
                PACK2U(v0, e0.y, e0.y); PACK2U(v1, e1.y, e1.y);
                PACK2U(v2, e2.y, e2.y); PACK2U(v3, e3.y, e3.y);
                FMA2(hp, v0, x0, hp); FMA2(hp, v1, x1, hp);
                FMA2(hp, v2, x2, hp); FMA2(hp, v3, x3, hp);
            }
            for (; j < end; j++) {
                int2 e0 = g_edge[j];
                unsigned long long x0 = xb8[(size_t)e0.x * 32 + lane];
                unsigned long long v0;
                PACK2U(v0, e0.y, e0.y);
                FMA2(hp, v0, x0, hp);
            }
            unsigned ulo, uhi;
            UNPACK2U(ulo, uhi, hp);
            hx[rr] = __uint_as_float(ulo);
            hy[rr] = __uint_as_float(uhi);
        }
        // transpose via two STS.128 (rows packed in components)
        h4w[2 * lane]     = make_float4(hx[0], hx[1], hx[2], hx[3]);
        h4w[2 * lane + 1] = make_float4(hy[0], hy[1], hy[2], hy[3]);
        __syncwarp();

        // --- GEMM: acc[r] = packed cols (2l, 2l+1) of output row r ---
        unsigned long long acc[4];
        #pragma unroll
        for (int rr = 0; rr < 4; rr++) {
            float2 xv = ((const float2*)x)[(size_t)(r0 + rr) * 32 + lane];
            float a0 = bs[2 * lane] + xv.x;
            float a1 = bs[2 * lane + 1] + xv.y;
            PACK2U(acc[rr], __float_as_uint(a0), __float_as_uint(a1));
        }

        #pragma unroll
        for (int p = 0; p < 32; p++) {
            ulonglong2 wv = Wp2[p * 32 + lane];      // k=2p (lo pair), k=2p+1 (hi pair)
            float4 ha = h4w[2 * p];                  // 4 rows' h at k=2p
            float4 hb = h4w[2 * p + 1];              // 4 rows' h at k=2p+1
            unsigned long long dd;
            unsigned u;
            u = __float_as_uint(ha.x); PACK2U(dd, u, u); FMA2(acc[0], dd, wv.x, acc[0]);
            u = __float_as_uint(hb.x); PACK2U(dd, u, u); FMA2(acc[0], dd, wv.y, acc[0]);
            u = __float_as_uint(ha.y); PACK2U(dd, u, u); FMA2(acc[1], dd, wv.x, acc[1]);
            u = __float_as_uint(hb.y); PACK2U(dd, u, u); FMA2(acc[1], dd, wv.y, acc[1]);
            u = __float_as_uint(ha.z); PACK2U(dd, u, u); FMA2(acc[2], dd, wv.x, acc[2]);
            u = __float_as_uint(hb.z); PACK2U(dd, u, u); FMA2(acc[2], dd, wv.y, acc[2]);
            u = __float_as_uint(ha.w); PACK2U(dd, u, u); FMA2(acc[3], dd, wv.x, acc[3]);
            u = __float_as_uint(hb.w); PACK2U(dd, u, u); FMA2(acc[3], dd, wv.y, acc[3]);
        }

        #pragma unroll
        for (int rr = 0; rr < 4; rr++) {
            unsigned ulo, uhi;
            UNPACK2U(ulo, uhi, acc[rr]);
            float o0 = __uint_as_float(ulo);
            float o1 = __uint_as_float(uhi);
            ((float2*)y)[(size_t)(r0 + rr) * 32 + lane] = make_float2(o0, o1);
            s0 += o0; s1 += o1;
            q0 = fmaf(o0, o0, q0);
            q1 = fmaf(o1, o1, q1);
        }
        __syncwarp();
    }

    atomicAdd(&rs[2 * lane],     s0);
    atomicAdd(&rs[2 * lane + 1], s1);
    atomicAdd(&rq[2 * lane],     q0);
    atomicAdd(&rq[2 * lane + 1], q1);
    __syncthreads();
    if (tid < D) {
        atomicAdd(&g_sum[tid], rs[tid]);
        atomicAdd(&g_sq[tid],  rq[tid]);
    }
}

// ---------------------------------------------------------------------------
// 6) BatchNorm + ReLU in-place
// ---------------------------------------------------------------------------
__global__ void bn_kernel(const float* __restrict__ gamma,
                          const float* __restrict__ beta,
                          float* __restrict__ y) {
    __shared__ float sc[D];
    __shared__ float sh[D];
    int tid = threadIdx.x;
    if (tid < D) {
        const float invN = 1.0f / (float)NN;
        float mean = g_sum[tid] * invN;
        float var  = g_sq[tid] * invN - mean * mean;
        float s = gamma[tid] * rsqrtf(var + EPS);
        sc[tid] = s;
        sh[tid] = beta[tid] - mean * s;
    }
    __syncthreads();

    size_t idx = (size_t)blockIdx.x * blockDim.x + threadIdx.x;
    size_t total = (size_t)NN * D / 4;
    if (idx < total) {
        float4 v = ((float4*)y)[idx];
        int c = (int)((idx * 4) & 63);
        v.x = fmaxf(fmaf(v.x, sc[c],     sh[c]),     0.f);
        v.y = fmaxf(fmaf(v.y, sc[c + 1], sh[c + 1]), 0.f);
        v.z = fmaxf(fmaf(v.z, sc[c + 2], sh[c + 2]), 0.f);
        v.w = fmaxf(fmaf(v.w, sc[c + 3], sh[c + 3]), 0.f);
        ((float4*)y)[idx] = v;
    }
}

// ---------------------------------------------------------------------------
// Launch. Input order: x, adj_val, W, b, gamma, beta, adj_row, adj_col
// ---------------------------------------------------------------------------
extern "C" void kernel_launch(void* const* d_in, const int* in_sizes, int n_in,
                              void* d_out, int out_size) {
    const float* x       = (const float*)d_in[0];
    const float* adj_val = (const float*)d_in[1];
    const float* W       = (const float*)d_in[2];
    const float* b       = (const float*)d_in[3];
    const float* gamma   = (const float*)d_in[4];
    const float* beta    = (const float*)d_in[5];
    const int*   adj_row = (const int*)d_in[6];
    const int*   adj_col = (const int*)d_in[7];
    float* y = (float*)d_out;

    hist_kernel<<<(NE / 4 + 255) / 256, 256>>>(adj_row);
    scan_local_kernel<<<NB, SCAN_BLK>>>();
    scan_add_kernel<<<NB, SCAN_BLK>>>();
    scatter_kernel<<<(NE / 4 + 255) / 256, 256>>>(adj_val, adj_row, adj_col);
    fused_kernel<<<1184, 256>>>(x, W, b, y);
    bn_kernel<<<(NN * D / 4 + 255) / 256, 256>>>(gamma, beta, y);
}

// round 5
// speedup vs baseline: 1.4113x; 1.1383x over previous
#include <cuda_runtime.h>
#include <cuda_bf16.h>

#define NN 100000
#define NE 1600000
#define D 64
#define EPS 1e-5f
#define SCAN_BLK 1024
#define NB 98                 // ceil(NN / SCAN_BLK)
#define NBLK 148              // csr_build grid: 1 block/SM, all resident

// Scratch (__device__ globals; zero-initialized at module load)
__device__ unsigned g_tickets;          // monotonic grid-barrier tickets
__device__ int   g_cnt[NN];
__device__ int   g_rowstart[NN + 1];
__device__ int   g_woff[NN];
__device__ int   g_blksum[NB];
__device__ int2  g_edge[NE];            // (col, val-bits), row-sorted
__device__ float g_sum[D];
__device__ float g_sq[D];

// Packed fp32x2 helpers (FFMA2 only reachable via PTX)
#define FMA2(d, a, b, c) asm("fma.rn.f32x2 %0, %1, %2, %3;" : "=l"(d) : "l"(a), "l"(b), "l"(c))
#define PACK2U(d, lo, hi) asm("mov.b64 %0, {%1, %2};" : "=l"(d) : "r"(lo), "r"(hi))
#define UNPACK2U(lo, hi, v) asm("mov.b64 {%0, %1}, %2;" : "=r"(lo), "=r"(hi) : "l"(v))

// ---------------------------------------------------------------------------
// Software grid barrier: monotonic tickets (replay-safe, no reset needed).
// Requires all NBLK blocks resident (148 blocks, 1024 thr => 1 block/SM).
// ---------------------------------------------------------------------------
__device__ __forceinline__ void grid_barrier() {
    __syncthreads();
    if (threadIdx.x == 0) {
        __threadfence();
        unsigned t = atomicAdd(&g_tickets, 1u) + 1u;
        unsigned target = ((t + NBLK - 1u) / NBLK) * NBLK;
        while (*(volatile unsigned*)&g_tickets < target) { }
        __threadfence();
    }
    __syncthreads();
}

// ---------------------------------------------------------------------------
// One-kernel CSR build: hist -> local scan -> block offsets -> scatter
// ---------------------------------------------------------------------------
__global__ void __launch_bounds__(SCAN_BLK) csr_build_kernel(
        const float* __restrict__ val,
        const int*   __restrict__ row,
        const int*   __restrict__ col) {
    const int tid = threadIdx.x;
    const int bid = blockIdx.x;
    const int gtid = bid * SCAN_BLK + tid;
    const int nthreads = NBLK * SCAN_BLK;

    // Phase 1: histogram (g_cnt zeroed by previous call's phase 2 / load-time)
    for (int t = gtid; t < NE / 4; t += nthreads) {
        int4 r4 = ((const int4*)row)[t];
        atomicAdd(&g_cnt[r4.x], 1);
        atomicAdd(&g_cnt[r4.y], 1);
        atomicAdd(&g_cnt[r4.z], 1);
        atomicAdd(&g_cnt[r4.w], 1);
    }
    if (bid == 0 && tid < D) { g_sum[tid] = 0.f; g_sq[tid] = 0.f; }

    grid_barrier();

    // Phase 2: per-chunk exclusive scan (first NB blocks); zero g_cnt for next call
    if (bid < NB) {
        int i = bid * SCAN_BLK + tid;
        int v = (i < NN) ? g_cnt[i] : 0;
        if (i < NN) g_cnt[i] = 0;
        int lane = tid & 31, w = tid >> 5;
        int s = v;
        #pragma unroll
        for (int d = 1; d < 32; d <<= 1) {
            int t = __shfl_up_sync(0xFFFFFFFFu, s, d);
            if (lane >= d) s += t;
        }
        __shared__ int wsum[32];
        if (lane == 31) wsum[w] = s;
        __syncthreads();
        if (w == 0) {
            int ws = wsum[lane];
            #pragma unroll
            for (int d = 1; d < 32; d <<= 1) {
                int t = __shfl_up_sync(0xFFFFFFFFu, ws, d);
                if (lane >= d) ws += t;
            }
            wsum[lane] = ws;
        }
        __syncthreads();
        int incl = s + (w > 0 ? wsum[w - 1] : 0);
        if (i < NN) g_rowstart[i] = incl - v;      // chunk-local exclusive
        if (tid == SCAN_BLK - 1) g_blksum[bid] = incl;
    }

    grid_barrier();

    // Phase 3: add block offsets, init write cursors
    if (bid < NB) {
        __shared__ int bsum[NB];
        __shared__ int boff_sh;
        if (tid < NB) bsum[tid] = g_blksum[tid];
        __syncthreads();
        if (tid == 0) {
            int o = 0;
            for (int k = 0; k < bid; k++) o += bsum[k];
            boff_sh = o;
        }
        __syncthreads();
        int i = bid * SCAN_BLK + tid;
        if (i < NN) {
            int rv = g_rowstart[i] + boff_sh;
            g_rowstart[i] = rv;
            g_woff[i] = rv;
        }
    }
    if (bid == 0 && tid == 0) g_rowstart[NN] = NE;

    grid_barrier();

    // Phase 4: scatter edges into row-sorted order (4 independent chains/thread)
    for (int t = gtid; t < NE / 4; t += nthreads) {
        int4   r4 = ((const int4*)row)[t];
        int4   c4 = ((const int4*)col)[t];
        float4 v4 = ((const float4*)val)[t];
        int p0 = atomicAdd(&g_woff[r4.x], 1);
        int p1 = atomicAdd(&g_woff[r4.y], 1);
        int p2 = atomicAdd(&g_woff[r4.z], 1);
        int p3 = atomicAdd(&g_woff[r4.w], 1);
        g_edge[p0] = make_int2(c4.x, __float_as_int(v4.x));
        g_edge[p1] = make_int2(c4.y, __float_as_int(v4.y));
        g_edge[p2] = make_int2(c4.z, __float_as_int(v4.z));
        g_edge[p3] = make_int2(c4.w, __float_as_int(v4.w));
    }
}

// ---------------------------------------------------------------------------
// Fused: h = A@x (CSR gather, 8 rows/warp) ; y = h@W^T + x ; BN stats.
// Bias b dropped: BN with batch stats is invariant to constant column shift.
// ---------------------------------------------------------------------------
#define HPAD(i) ((i) + ((i) >> 2))     // pad 16B per 64B: 4-way max conflicts

__global__ void __launch_bounds__(256) fused_kernel(const float* __restrict__ x,
                                                    const float* __restrict__ W,
                                                    float* __restrict__ y) {
    // Wp[p*32+l] = (Wt[2p][2l], Wt[2p][2l+1], Wt[2p+1][2l], Wt[2p+1][2l+1]),
    // Wt[k][j] = W[j*D+k]
    __shared__ float4 Wp[32 * 32];     // 16KB
    __shared__ float4 Hs[8][160];      // padded: logical 128 float4 per warp
    __shared__ float  rs[D];
    __shared__ float  rq[D];

    int tid = threadIdx.x;
    for (int idx = tid; idx < 1024; idx += 256) {
        int p = idx >> 5, l = idx & 31;
        Wp[idx] = make_float4(W[(2 * l) * D + 2 * p],     W[(2 * l + 1) * D + 2 * p],
                              W[(2 * l) * D + 2 * p + 1], W[(2 * l + 1) * D + 2 * p + 1]);
    }
    if (tid < D) { rs[tid] = 0.f; rq[tid] = 0.f; }
    __syncthreads();

    int w = tid >> 5;
    int lane = tid & 31;
    const unsigned long long* xb8 = (const unsigned long long*)x;  // (x[2l],x[2l+1])
    const ulonglong2* Wp2 = (const ulonglong2*)Wp;
    float4* Hw = Hs[w];

    float s0 = 0.f, s1 = 0.f, q0 = 0.f, q1 = 0.f;
    const int ngroups = NN / 8;        // 12500

    for (int g = blockIdx.x * 8 + w; g < ngroups; g += gridDim.x * 8) {
        int r0 = g * 8;

        // --- gather 8 rows; lane accumulates its 2 columns per row ---
        float hx[8], hy[8];
        #pragma unroll
        for (int rr = 0; rr < 8; rr++) {
            int r = r0 + rr;
            int start = g_rowstart[r];
            int end   = g_rowstart[r + 1];
            unsigned long long hp = 0ull;            // packed (hx,hy)
            int j = start;
            int end8 = start + ((end - start) & ~7);
            for (; j < end8; j += 8) {
                int2 e[8];
                #pragma unroll
                for (int u = 0; u < 8; u++) e[u] = g_edge[j + u];
                unsigned long long xv[8];
                #pragma unroll
                for (int u = 0; u < 8; u++)
                    xv[u] = xb8[(size_t)e[u].x * 32 + lane];
                #pragma unroll
                for (int u = 0; u < 8; u++) {
                    unsigned long long vv;
                    PACK2U(vv, e[u].y, e[u].y);
                    FMA2(hp, vv, xv[u], hp);
                }
            }
            for (; j < end; j++) {
                int2 e0 = g_edge[j];
                unsigned long long x0 = xb8[(size_t)e0.x * 32 + lane];
                unsigned long long vv;
                PACK2U(vv, e0.y, e0.y);
                FMA2(hp, vv, x0, hp);
            }
            unsigned ulo, uhi;
            UNPACK2U(ulo, uhi, hp);
            hx[rr] = __uint_as_float(ulo);
            hy[rr] = __uint_as_float(uhi);
        }
        // transpose: logical Hw[2k]=rows0-3 of col k, Hw[2k+1]=rows4-7
        Hw[5 * lane + 0] = make_float4(hx[0], hx[1], hx[2], hx[3]);  // col 2l, r0-3
        Hw[5 * lane + 1] = make_float4(hx[4], hx[5], hx[6], hx[7]);  // col 2l, r4-7
        Hw[5 * lane + 2] = make_float4(hy[0], hy[1], hy[2], hy[3]);  // col 2l+1
        Hw[5 * lane + 3] = make_float4(hy[4], hy[5], hy[6], hy[7]);
        __syncwarp();

        // --- GEMM: acc[r] = packed cols (2l, 2l+1) of output row r0+r ---
        unsigned long long acc[8];
        #pragma unroll
        for (int rr = 0; rr < 8; rr++)
            acc[rr] = xb8[(size_t)(r0 + rr) * 32 + lane];   // residual seed

        #pragma unroll
        for (int p = 0; p < 32; p++) {
            ulonglong2 wv = Wp2[p * 32 + lane];   // .x: k=2p pair, .y: k=2p+1 pair
            float4 alo = Hw[5 * p + 0];           // col 2p,   rows 0-3
            float4 ahi = Hw[5 * p + 1];           // col 2p,   rows 4-7
            float4 blo = Hw[5 * p + 2];           // col 2p+1, rows 0-3
            float4 bhi = Hw[5 * p + 3];           // col 2p+1, rows 4-7
            unsigned long long dd;
            unsigned u;
            u = __float_as_uint(alo.x); PACK2U(dd, u, u); FMA2(acc[0], dd, wv.x, acc[0]);
            u = __float_as_uint(blo.x); PACK2U(dd, u, u); FMA2(acc[0], dd, wv.y, acc[0]);
            u = __float_as_uint(alo.y); PACK2U(dd, u, u); FMA2(acc[1], dd, wv.x, acc[1]);
            u = __float_as_uint(blo.y); PACK2U(dd, u, u); FMA2(acc[1], dd, wv.y, acc[1]);
            u = __float_as_uint(alo.z); PACK2U(dd, u, u); FMA2(acc[2], dd, wv.x, acc[2]);
            u = __float_as_uint(blo.z); PACK2U(dd, u, u); FMA2(acc[2], dd, wv.y, acc[2]);
            u = __float_as_uint(alo.w); PACK2U(dd, u, u); FMA2(acc[3], dd, wv.x, acc[3]);
            u = __float_as_uint(blo.w); PACK2U(dd, u, u); FMA2(acc[3], dd, wv.y, acc[3]);
            u = __float_as_uint(ahi.x); PACK2U(dd, u, u); FMA2(acc[4], dd, wv.x, acc[4]);
            u = __float_as_uint(bhi.x); PACK2U(dd, u, u); FMA2(acc[4], dd, wv.y, acc[4]);
            u = __float_as_uint(ahi.y); PACK2U(dd, u, u); FMA2(acc[5], dd, wv.x, acc[5]);
            u = __float_as_uint(bhi.y); PACK2U(dd, u, u); FMA2(acc[5], dd, wv.y, acc[5]);
            u = __float_as_uint(ahi.z); PACK2U(dd, u, u); FMA2(acc[6], dd, wv.x, acc[6]);
            u = __float_as_uint(bhi.z); PACK2U(dd, u, u); FMA2(acc[6], dd, wv.y, acc[6]);
            u = __float_as_uint(ahi.w); PACK2U(dd, u, u); FMA2(acc[7], dd, wv.x, acc[7]);
            u = __float_as_uint(bhi.w); PACK2U(dd, u, u); FMA2(acc[7], dd, wv.y, acc[7]);
        }

        #pragma unroll
        for (int rr = 0; rr < 8; rr++) {
            unsigned ulo, uhi;
            UNPACK2U(ulo, uhi, acc[rr]);
            float o0 = __uint_as_float(ulo);
            float o1 = __uint_as_float(uhi);
            ((float2*)y)[(size_t)(r0 + rr) * 32 + lane] = make_float2(o0, o1);
            s0 += o0; s1 += o1;
            q0 = fmaf(o0, o0, q0);
            q1 = fmaf(o1, o1, q1);
        }
        __syncwarp();
    }

    atomicAdd(&rs[2 * lane],     s0);
    atomicAdd(&rs[2 * lane + 1], s1);
    atomicAdd(&rq[2 * lane],     q0);
    atomicAdd(&rq[2 * lane + 1], q1);
    __syncthreads();
    if (tid < D) {
        atomicAdd(&g_sum[tid], rs[tid]);
        atomicAdd(&g_sq[tid],  rq[tid]);
    }
}

// ---------------------------------------------------------------------------
// BatchNorm + ReLU in-place, 4 strided float4 per thread (MLP 4)
// ---------------------------------------------------------------------------
__global__ void bn_kernel(const float* __restrict__ gamma,
                          const float* __restrict__ beta,
                          float* __restrict__ y) {
    __shared__ float sc[D];
    __shared__ float sh[D];
    int tid = threadIdx.x;
    if (tid < D) {
        const float invN = 1.0f / (float)NN;
        float mean = g_sum[tid] * invN;
        float var  = g_sq[tid] * invN - mean * mean;
        float s = gamma[tid] * rsqrtf(var + EPS);
        sc[tid] = s;
        sh[tid] = beta[tid] - mean * s;
    }
    __syncthreads();

    const int total4 = NN * D / 4;                 // 1.6M
    const int stride = gridDim.x * blockDim.x;     // ~400k / 4 threads
    int idx = blockIdx.x * blockDim.x + threadIdx.x;

    float4 v[4];
    int id[4];
    #pragma unroll
    for (int u = 0; u < 4; u++) {
        id[u] = idx + u * stride;
        if (id[u] < total4) v[u] = ((float4*)y)[id[u]];
    }
    #pragma unroll
    for (int u = 0; u < 4; u++) {
        if (id[u] < total4) {
            int c = (id[u] * 4) & 63;
            float4 t = v[u];
            t.x = fmaxf(fmaf(t.x, sc[c],     sh[c]),     0.f);
            t.y = fmaxf(fmaf(t.y, sc[c + 1], sh[c + 1]), 0.f);
            t.z = fmaxf(fmaf(t.z, sc[c + 2], sh[c + 2]), 0.f);
            t.w = fmaxf(fmaf(t.w, sc[c + 3], sh[c + 3]), 0.f);
            ((float4*)y)[id[u]] = t;
        }
    }
}

// ---------------------------------------------------------------------------
// Launch. Input order: x, adj_val, W, b, gamma, beta, adj_row, adj_col
// ---------------------------------------------------------------------------
extern "C" void kernel_launch(void* const* d_in, const int* in_sizes, int n_in,
                              void* d_out, int out_size) {
    const float* x       = (const float*)d_in[0];
    const float* adj_val = (const float*)d_in[1];
    const float* W       = (const float*)d_in[2];
    const float* gamma   = (const float*)d_in[4];
    const float* beta    = (const float*)d_in[5];
    const int*   adj_row = (const int*)d_in[6];
    const int*   adj_col = (const int*)d_in[7];
    float* y = (float*)d_out;

    csr_build_kernel<<<NBLK, SCAN_BLK>>>(adj_val, adj_row, adj_col);
    fused_kernel<<<592, 256>>>(x, W, y);
    {
        int total4 = NN * D / 4;
        int blocks = (total4 / 4 + 255) / 256;     // 4 float4 per thread
        bn_kernel<<<blocks, 256>>>(gamma, beta, y);
    }
}